// round 11
// baseline (speedup 1.0000x reference)
#include <cuda_runtime.h>
#include <cuda_fp16.h>
#include <cstdint>

// ---------------- Problem constants ----------------
#define BATCH   8192
#define DH      1024
#define TILE_M  128             // batch rows per tile
#define JBLK    32              // hidden cols per tile (per gate)
#define KCH     64              // K elems per chunk (fp16: 128B rows)
#define NCHUNK  32              // 2*1024/64
#define THREADS 256
#define NTILES  2048            // 32 j-blocks x 64 m-blocks
#define GRID    296             // 148 SMs x 2 CTAs (persistent)

// ---------------- fp16 scratch (pre-rounded inputs), offsets in halfs ----------------
#define SCR_X 0u
#define SCR_H 8388608u
#define SCR_W 16777216u          // 8 matrices of 1048576 halfs: Wi,Wf,Wo,Wc,Ui,Uf,Uo,Uc
__device__ __half g_scrh[25165824];   // ~50.3 MB static scratch

// ---------------- SMEM layout ----------------
// [0, 98304)        3 stages x (A 16KB + B 16KB)
// [98304, 115200)   c tile: 128 rows x 33 floats (pitch-padded, conflict-free)
#define A_BYTES     16384
#define STAGE_BYTES 32768
#define SM_C_OFF    98304
#define C_PITCH     33
#define SMEM_TOTAL  (98304 + TILE_M * C_PITCH * 4)   // 115200 -> 2 CTAs/SM

// ---------------- helpers ----------------
__device__ __forceinline__ uint32_t smem_u32(const void* p) {
    uint32_t a;
    asm("{ .reg .u64 t; cvta.to.shared.u64 t, %1; cvt.u32.u64 %0, t; }" : "=r"(a) : "l"(p));
    return a;
}
__device__ __forceinline__ void mma_f16(float* d, const uint32_t* a, const uint32_t* b) {
    asm volatile(
        "mma.sync.aligned.m16n8k16.row.col.f32.f16.f16.f32 "
        "{%0,%1,%2,%3}, {%4,%5,%6,%7}, {%8,%9}, {%0,%1,%2,%3};"
        : "+f"(d[0]), "+f"(d[1]), "+f"(d[2]), "+f"(d[3])
        : "r"(a[0]), "r"(a[1]), "r"(a[2]), "r"(a[3]), "r"(b[0]), "r"(b[1]));
}
#define LDSM4(r, addr)                                                            \
    asm volatile("ldmatrix.sync.aligned.m8n8.x4.shared.b16 {%0,%1,%2,%3}, [%4];"  \
        : "=r"((r)[0]), "=r"((r)[1]), "=r"((r)[2]), "=r"((r)[3]) : "r"(addr))
#define CP_ASYNC16(dst, src) \
    asm volatile("cp.async.cg.shared.global [%0], [%1], 16;" :: "r"(dst), "l"(src))
#define CP_ASYNC4(dst, src) \
    asm volatile("cp.async.ca.shared.global [%0], [%1], 4;" :: "r"(dst), "l"(src))
#define CP_COMMIT()  asm volatile("cp.async.commit_group;" ::: "memory")
#define CP_WAIT(n)   asm volatile("cp.async.wait_group %0;" :: "n"(n) : "memory")

__device__ __forceinline__ float fast_sigmoid(float v) { return 1.0f / (1.0f + __expf(-v)); }
__device__ __forceinline__ float fast_tanh(float v) {
    return 1.0f - 2.0f / (__expf(2.0f * v) + 1.0f);   // exact +/-1 at large |v|
}

// ---------------- merged rounding pass (fp32 -> fp16 RN), one launch ----------------
__global__ void __launch_bounds__(256)
round_all_kernel(const float* __restrict__ x, const float* __restrict__ h,
                 const float* __restrict__ p0, const float* __restrict__ p1,
                 const float* __restrict__ p2, const float* __restrict__ p3,
                 const float* __restrict__ p4, const float* __restrict__ p5,
                 const float* __restrict__ p6, const float* __restrict__ p7) {
    const int r  = blockIdx.x >> 9;
    const int bi = blockIdx.x & 511;
    const size_t off = ((size_t)bi * 256 + threadIdx.x) * 8;
    const float* src;
    size_t dst;
    if (r < 8) {
        src = x + (((size_t)r) << 20) + off;
        dst = SCR_X + (((size_t)r) << 20) + off;
    } else if (r < 16) {
        src = h + (((size_t)(r - 8)) << 20) + off;
        dst = SCR_H + (((size_t)(r - 8)) << 20) + off;
    } else {
        const int g = r - 16;
        const float* wp = (g == 0) ? p0 : (g == 1) ? p1 : (g == 2) ? p2 : (g == 3) ? p3
                         : (g == 4) ? p4 : (g == 5) ? p5 : (g == 6) ? p6 : p7;
        src = wp + off;
        dst = SCR_W + (((size_t)g) << 20) + off;
    }
    float4 v0 = *(const float4*)src;
    float4 v1 = *(const float4*)(src + 4);
    __half2 a0 = __floats2half2_rn(v0.x, v0.y), a1 = __floats2half2_rn(v0.z, v0.w);
    __half2 a2 = __floats2half2_rn(v1.x, v1.y), a3 = __floats2half2_rn(v1.z, v1.w);
    uint4 w = { *(uint32_t*)&a0, *(uint32_t*)&a1, *(uint32_t*)&a2, *(uint32_t*)&a3 };
    *(uint4*)(g_scrh + dst) = w;
}

// ---------------- stage producer: chunk cc (0..31) of tile (mb, jb) ----------------
__device__ __forceinline__ void issue_chunk(uint32_t st, int mb, int jb, int cc,
                                            int rA, int seg, uint32_t dA,
                                            const uint32_t* dB) {
    const int p = cc >> 4;               // 0: x/W, 1: h/U
    const int k = (cc & 15) * KCH;
    const __half* sa = g_scrh + (p ? SCR_H : SCR_X)
                     + (size_t)(mb * TILE_M + rA) * DH + seg * 8 + k;
    const __half* sw = g_scrh + SCR_W + (size_t)p * 4194304
                     + (size_t)(jb * JBLK + rA) * DH + seg * 8 + k;
#pragma unroll
    for (int i = 0; i < 4; i++)          // A rows rA + 32*i
        CP_ASYNC16(st + dA + i * 4096, sa + (size_t)i * 32 * DH);
#pragma unroll
    for (int g = 0; g < 4; g++)          // B: gate-interleaved rows
        CP_ASYNC16(st + A_BYTES + dB[g], sw + (size_t)g * 1048576);
}

// ---------------- persistent GEMM + fused LSTM kernel ----------------
__global__ void __launch_bounds__(THREADS, 2)
lstm_mma8_kernel(const float* __restrict__ bi, const float* __restrict__ bfv,
                 const float* __restrict__ bo, const float* __restrict__ bc,
                 const float* __restrict__ c,
                 float* __restrict__ out_h, float* __restrict__ out_c) {
    extern __shared__ char smem[];
    float* smf = (float*)smem;
    const uint32_t sb = smem_u32(smem);

    const int tid  = threadIdx.x;
    const int wid  = tid >> 5;
    const int lane = tid & 31;
    const int warp_m = wid >> 2;      // 0..1  (64 rows each)
    const int warp_n = wid & 3;       // 0..3  (8-col j-octave; ni = gate)

    // -------- producer addressing --------
    const int rA  = tid >> 3;                 // 0..31
    const int seg = tid & 7;                  // 16B granule within 128B row
    const uint32_t swz = (uint32_t)((seg ^ (rA & 7)) << 4);
    const uint32_t dA = (uint32_t)(rA * 128) + swz;
    uint32_t dB[4];                           // gate-interleaved B row offsets
#pragma unroll
    for (int g = 0; g < 4; g++)
        dB[g] = (uint32_t)(((rA >> 3) * 32 + g * 8 + (rA & 7)) * 128) + swz;

    // -------- consumer (ldmatrix) addressing --------
    const uint32_t l7x = (uint32_t)((lane & 7) << 4);
    const uint32_t aoffb = (uint32_t)((warp_m * 64 + (lane & 15)) * 128);
    const uint32_t koffA = (uint32_t)((lane >> 4) << 4);
    const uint32_t boffb = (uint32_t)(A_BYTES +
                          (warp_n * 32 + (lane & 7) + (((lane >> 4) & 1) << 3)) * 128);
    const uint32_t koffB = (uint32_t)(((lane >> 3) & 1) << 4);

    float acc[4][4][4];
#pragma unroll
    for (int mi = 0; mi < 4; mi++)
#pragma unroll
        for (int ni = 0; ni < 4; ni++)
#pragma unroll
            for (int r = 0; r < 4; r++) acc[mi][ni][r] = 0.0f;

    // -------- persistent tile loop --------
    int tile = blockIdx.x;                 // + GRID each round
    // prologue: chunks 0,1 of first tile
    issue_chunk(sb + 0 * STAGE_BYTES, tile >> 5, tile & 31, 0, rA, seg, dA, dB);
    CP_COMMIT();
    issue_chunk(sb + 1 * STAGE_BYTES, tile >> 5, tile & 31, 1, rA, seg, dA, dB);
    CP_COMMIT();

    int s = 0, u = 2;
#pragma unroll 1
    while (tile < NTILES) {
        const int mb = tile >> 5, jb = tile & 31;
        const int m0 = mb * TILE_M, j0 = jb * JBLK;
        const int tile_next = tile + GRID;

#pragma unroll 1
        for (int t = 0; t < NCHUNK; t++) {
            CP_WAIT(1);
            __syncthreads();
            const uint32_t stu = sb + u * STAGE_BYTES;
            if (t < 29) {
                issue_chunk(stu, mb, jb, t + 2, rA, seg, dA, dB);
            } else if (t == 29) {
                issue_chunk(stu, mb, jb, 31, rA, seg, dA, dB);
                // bundle the c tile of THIS tile: complete by t=31's CP_WAIT(1)
#pragma unroll
                for (int i = 0; i < 16; i++) {
                    const int q = tid + i * THREADS;      // 0..4095 floats
                    const int row = q >> 5, col = q & 31;
                    CP_ASYNC4(sb + SM_C_OFF + (uint32_t)(row * C_PITCH + col) * 4,
                              c + (size_t)(m0 + row) * DH + j0 + col);
                }
            } else if (tile_next < NTILES) {
                issue_chunk(stu, tile_next >> 5, tile_next & 31, t - 30, rA, seg, dA, dB);
            }
            CP_COMMIT();

            const uint32_t st = sb + s * STAGE_BYTES;
#pragma unroll
            for (int ks = 0; ks < 4; ks++) {
                const uint32_t kk = (uint32_t)((ks + wid) & 3);
                const uint32_t tA = (kk * 32 + koffA) ^ l7x;
                const uint32_t tB = (kk * 32 + koffB) ^ l7x;
                uint32_t b0[4], b1[4];
                LDSM4(b0, st + boffb + tB);           // gates 0,1
                LDSM4(b1, st + boffb + 2048 + tB);    // gates 2,3
#pragma unroll
                for (int mi = 0; mi < 4; mi++) {
                    uint32_t a[4];
                    LDSM4(a, st + aoffb + mi * 2048 + tA);
                    mma_f16(acc[mi][0], a, b0 + 0);   // gate i
                    mma_f16(acc[mi][1], a, b0 + 2);   // gate f
                    mma_f16(acc[mi][2], a, b1 + 0);   // gate o
                    mma_f16(acc[mi][3], a, b1 + 2);   // gate c~
                }
            }
            s = (s == 2) ? 0 : s + 1;
            u = (u == 2) ? 0 : u + 1;
        }

        // -------- register-local fused LSTM epilogue --------
        {
            const int q  = lane >> 2;
            const int tg = lane & 3;
            const int jl = warp_n * 8 + tg * 2;
            const int jg = j0 + jl;
            const float2 bI = *(const float2*)(bi  + jg);
            const float2 bF = *(const float2*)(bfv + jg);
            const float2 bO = *(const float2*)(bo  + jg);
            const float2 bC = *(const float2*)(bc  + jg);
            const float* csm = smf + SM_C_OFF / 4;
#pragma unroll
            for (int mi = 0; mi < 4; mi++)
#pragma unroll
                for (int rr = 0; rr < 2; rr++) {
                    const int mc = warp_m * 64 + mi * 16 + q + rr * 8;
                    float2 nh2, nc2;
                    {
                        const float vi = acc[mi][0][rr * 2] + bI.x;
                        const float vf = acc[mi][1][rr * 2] + bF.x;
                        const float vo = acc[mi][2][rr * 2] + bO.x;
                        const float vc = acc[mi][3][rr * 2] + bC.x;
                        const float ig = fast_sigmoid(vi), fg = fast_sigmoid(vf);
                        const float og = fast_sigmoid(vo), cg = fast_tanh(vc);
                        const float ci = csm[mc * C_PITCH + jl];
                        nc2.x = fg * ci + ig * cg;
                        nh2.x = og * fast_tanh(nc2.x);
                    }
                    {
                        const float vi = acc[mi][0][rr * 2 + 1] + bI.y;
                        const float vf = acc[mi][1][rr * 2 + 1] + bF.y;
                        const float vo = acc[mi][2][rr * 2 + 1] + bO.y;
                        const float vc = acc[mi][3][rr * 2 + 1] + bC.y;
                        const float ig = fast_sigmoid(vi), fg = fast_sigmoid(vf);
                        const float og = fast_sigmoid(vo), cg = fast_tanh(vc);
                        const float ci = csm[mc * C_PITCH + jl + 1];
                        nc2.y = fg * ci + ig * cg;
                        nh2.y = og * fast_tanh(nc2.y);
                    }
                    const size_t o = (size_t)(m0 + mc) * DH + jg;
                    *(float2*)(out_h + o) = nh2;
                    *(float2*)(out_c + o) = nc2;
                }
            // reset accumulators for next tile
#pragma unroll
            for (int mi = 0; mi < 4; mi++)
#pragma unroll
                for (int ni = 0; ni < 4; ni++)
#pragma unroll
                    for (int r = 0; r < 4; r++) acc[mi][ni][r] = 0.0f;
        }
        tile = tile_next;
    }
    CP_WAIT(0);
}

// ---------------- Host launch ----------------
extern "C" void kernel_launch(void* const* d_in, const int* in_sizes, int n_in,
                              void* d_out, int out_size) {
    const float* x  = (const float*)d_in[0];
    const float* h  = (const float*)d_in[1];
    const float* c  = (const float*)d_in[2];
    const float* Wi = (const float*)d_in[3];
    const float* bi = (const float*)d_in[4];
    const float* Ui = (const float*)d_in[5];
    const float* Wf = (const float*)d_in[6];
    const float* bf = (const float*)d_in[7];
    const float* Uf = (const float*)d_in[8];
    const float* Wo = (const float*)d_in[9];
    const float* bo = (const float*)d_in[10];
    const float* Uo = (const float*)d_in[11];
    const float* Wc = (const float*)d_in[12];
    const float* bc = (const float*)d_in[13];
    const float* Uc = (const float*)d_in[14];
    float* out_h = (float*)d_out;
    float* out_c = out_h + (size_t)BATCH * DH;

    static bool once = false;
    if (!once) {
        cudaFuncSetAttribute(lstm_mma8_kernel, cudaFuncAttributeMaxDynamicSharedMemorySize,
                             SMEM_TOTAL);
        once = true;
    }

    // 1) round all inputs to fp16 into scratch (single launch)
    round_all_kernel<<<12288, 256>>>(x, h, Wi, Wf, Wo, Wc, Ui, Uf, Uo, Uc);

    // 2) persistent GEMM + fused gates
    lstm_mma8_kernel<<<GRID, THREADS, SMEM_TOTAL>>>(bi, bf, bo, bc, c, out_h, out_c);
}